// round 3
// baseline (speedup 1.0000x reference)
#include <cuda_runtime.h>
#include <cuda_bf16.h>

#define HH   128
#define LBn  64
#define PWn  32
#define WLn  96
#define WC   65
#define WCP  68
#define NCTA 64
#define RPB  2

// ---------------- device scratch (no allocations allowed) ----------------
__device__ float g_FT[WLn * HH * HH];
__device__ float g_P[2][HH * HH];
__device__ float g_Wc[2][HH * WCP];
__device__ float g_vpart[NCTA][HH];
__device__ float g_spart[NCTA];
__device__ float g_qpart[NCTA][WCP];
__device__ float g_Vpart[PWn][NCTA][WCP];
__device__ float g_V[PWn][WCP];
__device__ unsigned int g_cnt;   // zero-init
__device__ unsigned int g_gen;   // zero-init

// Grid barrier: all NCTA CTAs co-resident (64 << 148 SMs, 1 CTA/SM at this
// occupancy). __threadfence() (gpu scope) emits CCTL.IVALL -> L1 invalidated,
// so plain loads after the barrier see other SMs' plain stores.
__device__ __forceinline__ void gbar() {
    __syncthreads();
    if (threadIdx.x == 0) {
        __threadfence();
        unsigned int g0 = atomicAdd(&g_gen, 0u);   // read BEFORE arriving
        unsigned int a  = atomicAdd(&g_cnt, 1u);
        if (a == NCTA - 1u) {
            atomicExch(&g_cnt, 0u);                // reset BEFORE release
            __threadfence();
            atomicExch(&g_gen, g0 + 1u);
        } else {
            while (atomicAdd(&g_gen, 0u) == g0) { }
        }
        __threadfence();
    }
    __syncthreads();
}

// ---------------------------------------------------------------------------
// Kernel 1: transpose the 96 F matrices (128x128) into g_FT.
// ---------------------------------------------------------------------------
__global__ void __launch_bounds__(256) transpose_f(const float* __restrict__ Fw) {
    const int t = blockIdx.x;
    __shared__ float s[32][33];
    const float* src = Fw + (size_t)t * HH * HH;
    float* dst = g_FT + (size_t)t * HH * HH;
    const int x = threadIdx.x & 31;
    const int y0 = threadIdx.x >> 5;   // 0..7
    for (int ti = 0; ti < 4; ti++) {
        for (int tj = 0; tj < 4; tj++) {
            #pragma unroll
            for (int yy = 0; yy < 32; yy += 8)
                s[y0 + yy][x] = src[(ti * 32 + y0 + yy) * HH + tj * 32 + x];
            __syncthreads();
            #pragma unroll
            for (int yy = 0; yy < 32; yy += 8)
                dst[(tj * 32 + y0 + yy) * HH + ti * 32 + x] = s[x][y0 + yy];
            __syncthreads();
        }
    }
}

// ---------------------------------------------------------------------------
// Kernel 2: persistent batch-independent Kalman recursion.
// CTA c owns rows [2c, 2c+1]; thread tid owns column j = tid.
// ---------------------------------------------------------------------------
__global__ void __launch_bounds__(128, 1) kalman_persist(
    const float* __restrict__ Fw, const float* __restrict__ Fb,
    const float* __restrict__ Hw, const float* __restrict__ Hb,
    const float* __restrict__ istate, const float* __restrict__ icov,
    const float* __restrict__ Q, const float* __restrict__ R)
{
    const int c = blockIdx.x, tid = threadIdx.x, row0 = c * RPB;

    __shared__ float  sh[HH];
    __shared__ float2 sF[HH];       // owned F rows, [k] -> (row0, row0+1)
    __shared__ float2 sA[HH];       // A1 = F_rows * P, [k]
    __shared__ float  sfb[RPB];
    __shared__ float  sured[4][RPB];
    __shared__ float  su[RPB];      // u at owned rows

    // init: P0 = init_cov, Wc0 col0 = init_state
    #pragma unroll
    for (int r = 0; r < RPB; r++) {
        g_P[0][(row0 + r) * HH + tid] = icov[(row0 + r) * HH + tid];
        if (tid < WC)
            g_Wc[0][(row0 + r) * WCP + tid] = (tid == 0) ? istate[row0 + r] : 0.f;
    }
    const float R0 = R[0];
    int cur = 0;
    gbar();

    // ======================= filter (64 steps) =======================
    for (int t = 0; t < LBn; t++) {
        sh[tid] = Hw[t * HH + tid];
        sF[tid] = make_float2(Fw[((size_t)t * HH + row0) * HH + tid],
                              Fw[((size_t)t * HH + row0 + 1) * HH + tid]);
        if (tid < RPB) sfb[tid] = Fb[t * HH + row0 + tid];
        const float hbv = Hb[t];
        __syncthreads();

        // pass 1: A1[r][j] = sum_k F[r][k] P[k][j]
        float2 a1 = make_float2(0.f, 0.f);
        {
            const float* Pc = g_P[cur];
            #pragma unroll 8
            for (int k = 0; k < HH; k++) {
                float p = Pc[k * HH + tid];
                float2 f = sF[k];
                a1.x += f.x * p; a1.y += f.y * p;
            }
        }
        sA[tid] = a1;
        __syncthreads();

        // pass 2: Ppred[r][j] = sum_k A1[r][k] FT[k][j] + Q[r][j]
        float pp0 = 0.f, pp1 = 0.f;
        {
            const float* FT = g_FT + (size_t)t * HH * HH;
            #pragma unroll 8
            for (int k = 0; k < HH; k++) {
                float ft = FT[k * HH + tid];
                float2 a = sA[k];
                pp0 += a.x * ft; pp1 += a.y * ft;
            }
            pp0 += Q[row0 * HH + tid];
            pp1 += (row0 + 1) < HH ? Q[(row0 + 1) * HH + tid] : 0.f;
        }

        const float h0 = sh[row0], h1 = sh[row0 + 1];

        // v partial: v[j] = sum_i h[i] Ppred[i][j]  (owned rows)
        g_vpart[c][tid] = h0 * pp0 + h1 * pp1;

        // u at owned rows: u[r] = sum_j Ppred[r][j] h[j]
        {
            const float hj = sh[tid];
            float u0 = pp0 * hj, u1 = pp1 * hj;
            #pragma unroll
            for (int o = 16; o > 0; o >>= 1) {
                u0 += __shfl_xor_sync(0xffffffffu, u0, o);
                u1 += __shfl_xor_sync(0xffffffffu, u1, o);
            }
            if ((tid & 31) == 0) { sured[tid >> 5][0] = u0; sured[tid >> 5][1] = u1; }
        }
        __syncthreads();
        if (tid < RPB) su[tid] = sured[0][tid] + sured[1][tid] + sured[2][tid] + sured[3][tid];
        __syncthreads();
        if (tid == 0) g_spart[c] = h0 * su[0] + h1 * su[1];

        // T pass: T[r][j] = sum_k F[r][k] Wc[k][j] (+ f_b on col 0)
        float t0 = 0.f, t1 = 0.f;
        if (tid < WC) {
            const float* Wcur = g_Wc[cur];
            #pragma unroll 8
            for (int k = 0; k < HH; k++) {
                float w = Wcur[k * WCP + tid];
                float2 f = sF[k];
                t0 += f.x * w; t1 += f.y * w;
            }
            if (tid == 0) { t0 += sfb[0]; t1 += sfb[1]; }
            g_qpart[c][tid] = h0 * t0 + h1 * t1;
        }

        gbar();   // partials visible everywhere

        // phase B: reduce S, v, q; write P_new, Wc_new
        float S = R0;
        #pragma unroll
        for (int cc = 0; cc < NCTA; cc++) S += g_spart[cc];
        const float invS = 1.f / S;
        const float K0 = su[0] * invS, K1 = su[1] * invS;

        float vj = 0.f;
        #pragma unroll
        for (int cc = 0; cc < NCTA; cc++) vj += g_vpart[cc][tid];

        const int nxt = cur ^ 1;
        g_P[nxt][row0 * HH + tid]       = pp0 - K0 * vj;
        g_P[nxt][(row0 + 1) * HH + tid] = pp1 - K1 * vj;

        if (tid < WC) {
            float qj = 0.f;
            #pragma unroll
            for (int cc = 0; cc < NCTA; cc++) qj += g_qpart[cc][tid];
            // resid coeffs over e: +1 at col t+1, -h_b at col 0, -q elsewhere
            const float adj = (tid == t + 1 ? 1.f : 0.f) - (tid == 0 ? hbv : 0.f);
            g_Wc[nxt][row0 * WCP + tid]       = t0 - K0 * qj + K0 * adj;
            g_Wc[nxt][(row0 + 1) * WCP + tid] = t1 - K1 * qj + K1 * adj;
        }

        gbar();   // P/Wc complete
        cur ^= 1;
    }

    // ======================= prediction (32 steps) =======================
    for (int t = LBn; t < WLn; t++) {
        sh[tid] = Hw[t * HH + tid];
        sF[tid] = make_float2(Fw[((size_t)t * HH + row0) * HH + tid],
                              Fw[((size_t)t * HH + row0 + 1) * HH + tid]);
        if (tid < RPB) sfb[tid] = Fb[t * HH + row0 + tid];
        __syncthreads();

        if (tid < WC) {
            float w0 = 0.f, w1 = 0.f;
            const float* Wcur = g_Wc[cur];
            #pragma unroll 8
            for (int k = 0; k < HH; k++) {
                float w = Wcur[k * WCP + tid];
                float2 f = sF[k];
                w0 += f.x * w; w1 += f.y * w;
            }
            if (tid == 0) { w0 += sfb[0]; w1 += sfb[1]; }
            const int nxt = cur ^ 1;
            g_Wc[nxt][row0 * WCP + tid]       = w0;
            g_Wc[nxt][(row0 + 1) * WCP + tid] = w1;
            const float h0 = sh[row0], h1 = sh[row0 + 1];
            g_Vpart[t - LBn][c][tid] = h0 * w0 + h1 * w1;
        }
        gbar();
        cur ^= 1;
    }

    // tail: CTA c < 32 reduces V row p = c
    if (c < PWn && tid < WC) {
        float s = 0.f;
        #pragma unroll
        for (int cc = 0; cc < NCTA; cc++) s += g_Vpart[c][cc][tid];
        if (tid == 0) s += Hb[LBn + c];
        g_V[c][tid] = s;
    }
}

// ---------------------------------------------------------------------------
// Kernel 3: out[b][p] = V[p][0] + sum_t V[p][1+t] x[b][t]
// warp = one batch row, lane = p -> coalesced stores; sV stride 65 conflict-free
// ---------------------------------------------------------------------------
__global__ void __launch_bounds__(256) out_gemm(
    const float* __restrict__ x, float* __restrict__ out)
{
    __shared__ float sV[PWn][WC];
    const int tid = threadIdx.x;
    for (int e = tid; e < PWn * WC; e += 256) {
        int p = e / WC, j = e % WC;
        sV[p][j] = g_V[p][j];
    }
    __syncthreads();

    const int gid = blockIdx.x * 256 + tid;
    const int b = gid >> 5, p = gid & 31;
    const float* xr = x + (size_t)b * LBn;
    float acc = sV[p][0];
    #pragma unroll 8
    for (int tt = 0; tt < LBn; tt++)
        acc += sV[p][1 + tt] * __ldg(xr + tt);   // warp-broadcast load
    out[(size_t)b * PWn + p] = acc;
}

// ---------------------------------------------------------------------------
extern "C" void kernel_launch(void* const* d_in, const int* in_sizes, int n_in,
                              void* d_out, int out_size) {
    const float* x   = (const float*)d_in[0];
    const float* Fw  = (const float*)d_in[1];
    const float* Fb  = (const float*)d_in[2];
    const float* Hw  = (const float*)d_in[3];
    const float* Hb  = (const float*)d_in[4];
    const float* ist = (const float*)d_in[5];
    const float* icv = (const float*)d_in[6];
    const float* Q   = (const float*)d_in[7];
    const float* R   = (const float*)d_in[8];

    transpose_f<<<WLn, 256>>>(Fw);
    kalman_persist<<<NCTA, 128>>>(Fw, Fb, Hw, Hb, ist, icv, Q, R);
    out_gemm<<<(8192 * PWn) / 256, 256>>>(x, (float*)d_out);
}

// round 4
// speedup vs baseline: 1.5061x; 1.5061x over previous
#include <cuda_runtime.h>
#include <cuda_bf16.h>

#define HH   128
#define LBn  64
#define PWn  32
#define WLn  96
#define WC   65
#define WCP  68
#define NCTA 64
#define TPB  256

// ---------------- device scratch (no allocations allowed) ----------------
__device__ float g_FT[WLn * HH * HH];
__device__ float g_P[2][HH * HH];
__device__ float g_Wc[2][HH * WCP];
__device__ float g_vpart[NCTA][HH];
__device__ float g_spart[NCTA];
__device__ float g_qpart[NCTA][WCP];
__device__ float g_Vpart[PWn][NCTA][WCP];
__device__ float g_V[PWn][WCP];
__device__ unsigned int g_cnt;   // zero-init
__device__ unsigned int g_gen;   // zero-init

__device__ __forceinline__ float comp2(float2 v, int h) { return h ? v.y : v.x; }

// Grid barrier: all NCTA CTAs co-resident (64 <= 148 SMs, 1 CTA/SM).
// __threadfence() (gpu scope) emits CCTL.IVALL -> L1 invalidated, so plain
// loads after the barrier observe other SMs' plain stores.
__device__ __forceinline__ void gbar() {
    __syncthreads();
    if (threadIdx.x == 0) {
        __threadfence();
        unsigned int g0 = atomicAdd(&g_gen, 0u);   // read BEFORE arriving
        unsigned int a  = atomicAdd(&g_cnt, 1u);
        if (a == NCTA - 1u) {
            atomicExch(&g_cnt, 0u);                // reset BEFORE release
            __threadfence();
            atomicExch(&g_gen, g0 + 1u);
        } else {
            while (atomicAdd(&g_gen, 0u) == g0) { }
        }
        __threadfence();
    }
    __syncthreads();
}

// ---------------------------------------------------------------------------
// Kernel 1: transpose the 96 F matrices (128x128) into g_FT.
// grid (96, 4): blockIdx.y = source row-block ti.
// ---------------------------------------------------------------------------
__global__ void __launch_bounds__(256) transpose_f(const float* __restrict__ Fw) {
    const int t  = blockIdx.x;
    const int ti = blockIdx.y;
    __shared__ float s[32][33];
    const float* src = Fw + (size_t)t * HH * HH;
    float* dst = g_FT + (size_t)t * HH * HH;
    const int x  = threadIdx.x & 31;
    const int y0 = threadIdx.x >> 5;   // 0..7
    for (int tj = 0; tj < 4; tj++) {
        #pragma unroll
        for (int yy = 0; yy < 32; yy += 8)
            s[y0 + yy][x] = src[(ti * 32 + y0 + yy) * HH + tj * 32 + x];
        __syncthreads();
        #pragma unroll
        for (int yy = 0; yy < 32; yy += 8)
            dst[(tj * 32 + y0 + yy) * HH + ti * 32 + x] = s[x][y0 + yy];
        __syncthreads();
    }
}

// ---------------------------------------------------------------------------
// Kernel 2: persistent batch-independent Kalman recursion.
// CTA c owns rows {2c, 2c+1}. Thread (j = tid&127, h = tid>>7):
//   - during k-loops: accumulates partial sums over k in [64h, 64h+64)
//   - after combine: owns column j of row (2c + h)
// ---------------------------------------------------------------------------
__global__ void __launch_bounds__(TPB, 1) kalman_persist(
    const float* __restrict__ Fw, const float* __restrict__ Fb,
    const float* __restrict__ Hw, const float* __restrict__ Hb,
    const float* __restrict__ istate, const float* __restrict__ icov,
    const float* __restrict__ Q, const float* __restrict__ R)
{
    const int c = blockIdx.x, tid = threadIdx.x;
    const int j = tid & 127, h = tid >> 7;
    const int row0 = c * 2;
    const int k0 = h * 64;
    const int myrow = row0 + h;

    __shared__ float  sh[HH];
    __shared__ float2 sF[HH];        // (F[row0][k], F[row0+1][k])
    __shared__ float2 sA1p[2][HH];   // pass-1 partials per half
    __shared__ float2 sA[HH];        // combined A1
    __shared__ float2 sPp[2][HH];    // pass-2 partials
    __shared__ float2 sTp[2][WC];    // T partials
    __shared__ float  svp[2][HH];    // v partials / phase-B v sums
    __shared__ float  sqp[2][WC];    // q partials / phase-B q sums
    __shared__ float  sured[2][4];   // u warp partials [h][warp-in-half]
    __shared__ float  su[2];         // u at owned rows
    __shared__ float  ss[NCTA];      // spart staging
    __shared__ float  sS;            // reduced S (includes R0)
    __shared__ float  sfb[2];

    // ---- init: P0 = init_cov, Wc0 col0 = init_state ----
    if (tid < HH) {
        g_P[0][row0 * HH + tid]       = icov[row0 * HH + tid];
        g_P[0][(row0 + 1) * HH + tid] = icov[(row0 + 1) * HH + tid];
        if (tid < WC) {
            g_Wc[0][row0 * WCP + tid]       = (tid == 0) ? istate[row0] : 0.f;
            g_Wc[0][(row0 + 1) * WCP + tid] = (tid == 0) ? istate[row0 + 1] : 0.f;
        }
    }
    const float R0 = R[0];
    int cur = 0;
    gbar();

    const bool doT = (j < WC);

    // ======================= filter (64 steps) =======================
    for (int t = 0; t < LBn; t++) {
        if (tid < HH) {
            sh[tid] = Hw[t * HH + tid];
            sF[tid] = make_float2(Fw[((size_t)t * HH + row0) * HH + tid],
                                  Fw[((size_t)t * HH + row0 + 1) * HH + tid]);
        }
        if (tid < 2) sfb[tid] = Fb[t * HH + row0 + tid];
        const float hbv = Hb[t];
        __syncthreads();

        // ---- loop A (fused): A1 partial (F*P) + T partial (F*Wc) ----
        float2 a1 = make_float2(0.f, 0.f);
        float2 tt = make_float2(0.f, 0.f);
        {
            const float* Pc = g_P[cur] + (size_t)k0 * HH + j;
            const float* Wcur = g_Wc[cur] + (size_t)k0 * WCP + j;
            #pragma unroll 8
            for (int kk = 0; kk < 64; kk++) {
                float2 f = sF[k0 + kk];
                float p = Pc[kk * HH];
                a1.x += f.x * p; a1.y += f.y * p;
                if (doT) {
                    float w = Wcur[kk * WCP];
                    tt.x += f.x * w; tt.y += f.y * w;
                }
            }
        }
        sA1p[h][j] = a1;
        if (doT) sTp[h][j] = tt;
        __syncthreads();
        if (tid < HH) {
            float2 u0 = sA1p[0][tid], u1 = sA1p[1][tid];
            sA[tid] = make_float2(u0.x + u1.x, u0.y + u1.y);
        }
        __syncthreads();

        // ---- loop B: Ppred partial = A1 * F^T ----
        float2 pp = make_float2(0.f, 0.f);
        {
            const float* FT = g_FT + (size_t)t * HH * HH + (size_t)k0 * HH + j;
            #pragma unroll 16
            for (int kk = 0; kk < 64; kk++) {
                float ft = FT[kk * HH];
                float2 a = sA[k0 + kk];
                pp.x += a.x * ft; pp.y += a.y * ft;
            }
        }
        sPp[h][j] = pp;
        __syncthreads();

        // combined per-(j,h): I own row (row0+h), column j
        float ppf = comp2(sPp[0][j], h) + comp2(sPp[1][j], h) + Q[myrow * HH + j];
        float ttf = 0.f;
        if (doT) {
            ttf = comp2(sTp[0][j], h) + comp2(sTp[1][j], h);
            if (j == 0) ttf += sfb[h];
        }

        const float hr = sh[myrow];
        // v / q partials for this CTA
        svp[h][j] = hr * ppf;
        if (doT) sqp[h][j] = hr * ttf;

        // u[h] = sum_j Ppred[row0+h][j] * h[j] : reduce over 128 j in my half
        {
            float uv = ppf * sh[j];
            #pragma unroll
            for (int o = 16; o > 0; o >>= 1)
                uv += __shfl_xor_sync(0xffffffffu, uv, o);
            if ((tid & 31) == 0) sured[h][(tid >> 5) & 3] = uv;
        }
        __syncthreads();
        if (tid < 2)
            su[tid] = sured[tid][0] + sured[tid][1] + sured[tid][2] + sured[tid][3];
        if (tid < HH)
            g_vpart[c][tid] = svp[0][tid] + svp[1][tid];
        else if (tid - HH < WC)
            g_qpart[c][tid - HH] = sqp[0][tid - HH] + sqp[1][tid - HH];
        __syncthreads();
        if (tid == 0)
            g_spart[c] = sh[row0] * su[0] + sh[row0 + 1] * su[1];

        gbar();   // barrier 1: all CTA partials visible

        // ---- phase B: reduce S, v, q over CTAs (split across halves) ----
        {
            float vs = 0.f, qs = 0.f;
            const int cc0 = h * 32;
            #pragma unroll 16
            for (int i = 0; i < 32; i++) vs += g_vpart[cc0 + i][j];
            svp[h][j] = vs;
            if (doT) {
                #pragma unroll 16
                for (int i = 0; i < 32; i++) qs += g_qpart[cc0 + i][j];
                sqp[h][j] = qs;
            }
            if (tid < NCTA) ss[tid] = g_spart[tid];
        }
        __syncthreads();
        if (tid < 32) {
            float v = ss[tid] + ss[tid + 32];
            #pragma unroll
            for (int o = 16; o > 0; o >>= 1)
                v += __shfl_xor_sync(0xffffffffu, v, o);
            if (tid == 0) sS = R0 + v;
        }
        __syncthreads();

        const float invS = 1.f / sS;
        const float K = su[h] * invS;
        const float vj = svp[0][j] + svp[1][j];
        const int nxt = cur ^ 1;
        g_P[nxt][myrow * HH + j] = ppf - K * vj;
        if (doT) {
            const float qj = sqp[0][j] + sqp[1][j];
            const float adj = (j == t + 1 ? 1.f : 0.f) - (j == 0 ? hbv : 0.f);
            g_Wc[nxt][myrow * WCP + j] = ttf - K * (qj - adj);
        }

        gbar();   // barrier 2: P/Wc complete
        cur ^= 1;
    }

    // ======================= prediction (32 steps) =======================
    for (int t = LBn; t < WLn; t++) {
        if (tid < HH) {
            sh[tid] = Hw[t * HH + tid];
            sF[tid] = make_float2(Fw[((size_t)t * HH + row0) * HH + tid],
                                  Fw[((size_t)t * HH + row0 + 1) * HH + tid]);
        }
        if (tid < 2) sfb[tid] = Fb[t * HH + row0 + tid];
        __syncthreads();

        float2 tt = make_float2(0.f, 0.f);
        if (doT) {
            const float* Wcur = g_Wc[cur] + (size_t)k0 * WCP + j;
            #pragma unroll 16
            for (int kk = 0; kk < 64; kk++) {
                float2 f = sF[k0 + kk];
                float w = Wcur[kk * WCP];
                tt.x += f.x * w; tt.y += f.y * w;
            }
            sTp[h][j] = tt;
        }
        __syncthreads();

        if (doT) {
            float wf = comp2(sTp[0][j], h) + comp2(sTp[1][j], h);
            if (j == 0) wf += sfb[h];
            const int nxt = cur ^ 1;
            g_Wc[nxt][myrow * WCP + j] = wf;
            sqp[h][j] = sh[myrow] * wf;
        }
        __syncthreads();
        if (tid < WC)
            g_Vpart[t - LBn][c][tid] = sqp[0][tid] + sqp[1][tid];

        gbar();
        cur ^= 1;
    }

    // tail: CTA c < 32 reduces V row p = c  (split across halves)
    if (c < PWn && doT) {
        float s = 0.f;
        const int cc0 = h * 32;
        #pragma unroll 16
        for (int i = 0; i < 32; i++) s += g_Vpart[c][cc0 + i][j];
        svp[h][j] = s;
    }
    __syncthreads();
    if (c < PWn && tid < WC) {
        float s = svp[0][tid] + svp[1][tid];
        if (tid == 0) s += Hb[LBn + c];
        g_V[c][tid] = s;
    }
}

// ---------------------------------------------------------------------------
// Kernel 3: out[b][p] = V[p][0] + sum_t V[p][1+t] x[b][t]
// warp = one batch row, lane = p -> coalesced stores.
// ---------------------------------------------------------------------------
__global__ void __launch_bounds__(256) out_gemm(
    const float* __restrict__ x, float* __restrict__ out)
{
    __shared__ float sV[PWn][WC];
    const int tid = threadIdx.x;
    for (int e = tid; e < PWn * WC; e += 256) {
        int p = e / WC, jj = e % WC;
        sV[p][jj] = g_V[p][jj];
    }
    __syncthreads();

    const int gid = blockIdx.x * 256 + tid;
    const int b = gid >> 5, p = gid & 31;
    const float* xr = x + (size_t)b * LBn;
    float acc = sV[p][0];
    #pragma unroll 8
    for (int tt = 0; tt < LBn; tt++)
        acc += sV[p][1 + tt] * __ldg(xr + tt);   // warp-broadcast load
    out[(size_t)b * PWn + p] = acc;
}

// ---------------------------------------------------------------------------
extern "C" void kernel_launch(void* const* d_in, const int* in_sizes, int n_in,
                              void* d_out, int out_size) {
    const float* x   = (const float*)d_in[0];
    const float* Fw  = (const float*)d_in[1];
    const float* Fb  = (const float*)d_in[2];
    const float* Hw  = (const float*)d_in[3];
    const float* Hb  = (const float*)d_in[4];
    const float* ist = (const float*)d_in[5];
    const float* icv = (const float*)d_in[6];
    const float* Q   = (const float*)d_in[7];
    const float* R   = (const float*)d_in[8];

    dim3 tgrid(WLn, 4);
    transpose_f<<<tgrid, 256>>>(Fw);
    kalman_persist<<<NCTA, TPB>>>(Fw, Fb, Hw, Hb, ist, icv, Q, R);
    out_gemm<<<(8192 * PWn) / 256, 256>>>(x, (float*)d_out);
}

// round 6
// speedup vs baseline: 1.9830x; 1.3167x over previous
#include <cuda_runtime.h>
#include <cuda_bf16.h>

#define HH   128
#define LBn  64
#define PWn  32
#define WLn  96
#define WC   65
#define WCP  68
#define NCTA 64
#define TPB  256

// ---------------- device scratch (no allocations allowed) ----------------
__device__ float g_FT[WLn * HH * HH];
__device__ float g_P[2][HH * HH];
__device__ float g_Wc[2][HH * WCP];
__device__ float g_vpart[NCTA][HH];
__device__ float g_spart[NCTA];
__device__ float g_qpart[NCTA][WCP];
__device__ float g_Vpart[PWn][NCTA][WCP];
__device__ float g_V[PWn][WCP];
__device__ unsigned int g_cnt;   // zero-init
__device__ unsigned int g_gen;   // zero-init

__device__ __forceinline__ float comp2(float2 v, int h) { return h ? v.y : v.x; }

// Grid barrier (round-4 proven protocol + nanosleep backoff in the poll).
// All NCTA CTAs co-resident (64 <= 148 SMs, 1 CTA/SM). __threadfence()
// (gpu scope) emits CCTL.IVALL -> L1 invalidated, so plain loads after the
// barrier observe other SMs' plain stores.
__device__ __forceinline__ void gbar() {
    __syncthreads();
    if (threadIdx.x == 0) {
        __threadfence();
        unsigned int g0 = atomicAdd(&g_gen, 0u);   // read BEFORE arriving
        unsigned int a  = atomicAdd(&g_cnt, 1u);
        if (a == NCTA - 1u) {
            atomicExch(&g_cnt, 0u);                // reset BEFORE release
            __threadfence();
            atomicExch(&g_gen, g0 + 1u);
        } else {
            while (atomicAdd(&g_gen, 0u) == g0) { __nanosleep(128); }
        }
        __threadfence();
    }
    __syncthreads();
}

// ---------------------------------------------------------------------------
// Kernel 1: transpose the 96 F matrices (128x128) into g_FT.
// ---------------------------------------------------------------------------
__global__ void __launch_bounds__(256) transpose_f(const float* __restrict__ Fw) {
    const int t  = blockIdx.x;
    const int ti = blockIdx.y;
    __shared__ float s[32][33];
    const float* src = Fw + (size_t)t * HH * HH;
    float* dst = g_FT + (size_t)t * HH * HH;
    const int x  = threadIdx.x & 31;
    const int y0 = threadIdx.x >> 5;
    for (int tj = 0; tj < 4; tj++) {
        #pragma unroll
        for (int yy = 0; yy < 32; yy += 8)
            s[y0 + yy][x] = src[(ti * 32 + y0 + yy) * HH + tj * 32 + x];
        __syncthreads();
        #pragma unroll
        for (int yy = 0; yy < 32; yy += 8)
            dst[(tj * 32 + y0 + yy) * HH + ti * 32 + x] = s[x][y0 + yy];
        __syncthreads();
    }
}

// ---------------------------------------------------------------------------
// Kernel 2: persistent batch-independent Kalman recursion.
// CTA c owns rows {2c, 2c+1}. Thread (j = tid&127, h = tid>>7):
//   - during k-loops: partial sums over k in [64h, 64h+64)
//   - after combine: owns column j of row (2c + h)
// Step parameters double-buffered; prefetch for step t+1 is issued just
// before the end-of-step barrier (its entry __syncthreads orders the writes).
// ---------------------------------------------------------------------------
__global__ void __launch_bounds__(TPB, 1) kalman_persist(
    const float* __restrict__ Fw, const float* __restrict__ Fb,
    const float* __restrict__ Hw, const float* __restrict__ Hb,
    const float* __restrict__ istate, const float* __restrict__ icov,
    const float* __restrict__ Q, const float* __restrict__ R)
{
    const int c = blockIdx.x, tid = threadIdx.x;
    const int j = tid & 127, h = tid >> 7;
    const int row0 = c * 2;
    const int k0 = h * 64;
    const int myrow = row0 + h;

    __shared__ float  sh[2][HH];      // H_w row, double buffered
    __shared__ float2 sF[2][HH];      // (F[row0][k], F[row0+1][k]), double buffered
    __shared__ float  sfbh[2][4];     // [buf][0..1]=F_b rows, [2]=H_b
    __shared__ float2 sA1p[2][HH];    // pass-1 partials per k-half
    __shared__ float2 sA[HH];         // combined A1
    __shared__ float2 sPp[2][HH];     // pass-2 partials
    __shared__ float2 sTp[2][WC];     // T partials
    __shared__ float  svp[2][HH];     // v partials / phase-B v sums
    __shared__ float  sqp[2][WC];     // q partials / phase-B q sums
    __shared__ float  sured[2][4];    // u warp partials [h][warp-in-half]
    __shared__ float  su[2];          // u at owned rows
    __shared__ float  ss[NCTA];       // spart staging
    __shared__ float  sS;             // reduced S (includes R0)

    // ---- init: P0 = init_cov, Wc0 col0 = init_state ----
    if (tid < HH) {
        g_P[0][row0 * HH + tid]       = icov[row0 * HH + tid];
        g_P[0][(row0 + 1) * HH + tid] = icov[(row0 + 1) * HH + tid];
        if (tid < WC) {
            g_Wc[0][row0 * WCP + tid]       = (tid == 0) ? istate[row0] : 0.f;
            g_Wc[0][(row0 + 1) * WCP + tid] = (tid == 0) ? istate[row0 + 1] : 0.f;
        }
    }
    const float R0 = R[0];

    // initial param load (buffer 0, step 0)
    if (tid < HH) {
        sh[0][tid] = Hw[tid];
        sF[0][tid] = make_float2(Fw[(size_t)row0 * HH + tid],
                                 Fw[(size_t)(row0 + 1) * HH + tid]);
    } else if (tid < HH + 2) {
        sfbh[0][tid - HH] = Fb[row0 + (tid - HH)];
    } else if (tid == HH + 2) {
        sfbh[0][2] = Hb[0];
    }

    int cur = 0, pb = 0;
    gbar();

    const bool doT = (j < WC);

    // ======================= filter (64 steps) =======================
    for (int t = 0; t < LBn; t++) {
        const float hbv = sfbh[pb][2];

        // ---- loop A (fused): A1 partial (F*P) + T partial (F*Wc) ----
        float2 a1 = make_float2(0.f, 0.f);
        float2 tv = make_float2(0.f, 0.f);
        {
            const float* Pc   = g_P[cur]  + (size_t)k0 * HH  + j;
            const float* Wcur = g_Wc[cur] + (size_t)k0 * WCP + j;
            #pragma unroll 32
            for (int kk = 0; kk < 64; kk++) {
                float2 f = sF[pb][k0 + kk];
                float p = Pc[kk * HH];
                a1.x += f.x * p; a1.y += f.y * p;
                if (doT) {
                    float w = Wcur[kk * WCP];
                    tv.x += f.x * w; tv.y += f.y * w;
                }
            }
        }
        sA1p[h][j] = a1;
        if (doT) sTp[h][j] = tv;
        __syncthreads();
        if (tid < HH) {
            float2 u0 = sA1p[0][tid], u1 = sA1p[1][tid];
            sA[tid] = make_float2(u0.x + u1.x, u0.y + u1.y);
        }
        __syncthreads();

        // ---- loop B: Ppred partial = A1 * F^T ----
        float2 pp = make_float2(0.f, 0.f);
        {
            const float* FT = g_FT + (size_t)t * HH * HH + (size_t)k0 * HH + j;
            #pragma unroll 32
            for (int kk = 0; kk < 64; kk++) {
                float ft = FT[kk * HH];
                float2 a = sA[k0 + kk];
                pp.x += a.x * ft; pp.y += a.y * ft;
            }
        }
        sPp[h][j] = pp;
        __syncthreads();

        // combined per-(j,h): I own row (row0+h), column j
        float ppf = comp2(sPp[0][j], h) + comp2(sPp[1][j], h) + Q[myrow * HH + j];
        float ttf = 0.f;
        if (doT) {
            ttf = comp2(sTp[0][j], h) + comp2(sTp[1][j], h);
            if (j == 0) ttf += sfbh[pb][h];
        }

        const float hr = sh[pb][myrow];
        svp[h][j] = hr * ppf;
        if (doT) sqp[h][j] = hr * ttf;

        // u[h] = sum_j Ppred[row0+h][j] * h[j]
        {
            float uv = ppf * sh[pb][j];
            #pragma unroll
            for (int o = 16; o > 0; o >>= 1)
                uv += __shfl_xor_sync(0xffffffffu, uv, o);
            if ((tid & 31) == 0) sured[h][(tid >> 5) & 3] = uv;
        }
        __syncthreads();
        if (tid < 2)
            su[tid] = sured[tid][0] + sured[tid][1] + sured[tid][2] + sured[tid][3];
        if (tid < HH)
            g_vpart[c][tid] = svp[0][tid] + svp[1][tid];
        else if (tid - HH < WC)
            g_qpart[c][tid - HH] = sqp[0][tid - HH] + sqp[1][tid - HH];
        __syncthreads();
        if (tid == 0)
            g_spart[c] = sh[pb][row0] * su[0] + sh[pb][row0 + 1] * su[1];

        gbar();   // barrier 1: partials visible

        // ---- phase B: reduce S, v, q over CTAs (split across halves) ----
        {
            float vs = 0.f;
            const int cc0 = h * 32;
            #pragma unroll
            for (int i = 0; i < 32; i++) vs += g_vpart[cc0 + i][j];
            svp[h][j] = vs;
            if (doT) {
                float qs = 0.f;
                #pragma unroll
                for (int i = 0; i < 32; i++) qs += g_qpart[cc0 + i][j];
                sqp[h][j] = qs;
            }
            if (tid < NCTA) ss[tid] = g_spart[tid];
        }
        __syncthreads();
        if (tid < 32) {
            float v = ss[tid] + ss[tid + 32];
            #pragma unroll
            for (int o = 16; o > 0; o >>= 1)
                v += __shfl_xor_sync(0xffffffffu, v, o);
            if (tid == 0) sS = R0 + v;
        }
        __syncthreads();

        const float invS = 1.f / sS;
        const float K = su[h] * invS;
        const float vj = svp[0][j] + svp[1][j];
        const int nxt = cur ^ 1;
        g_P[nxt][myrow * HH + j] = ppf - K * vj;
        if (doT) {
            const float qj = sqp[0][j] + sqp[1][j];
            const float adj = (j == t + 1 ? 1.f : 0.f) - (j == 0 ? hbv : 0.f);
            g_Wc[nxt][myrow * WCP + j] = ttf - K * (qj - adj);
        }

        // prefetch step t+1 params into the other buffer (ordered by gbar's
        // entry __syncthreads; consumed only after the barrier)
        {
            const int t1 = t + 1, nb = pb ^ 1;
            if (tid < HH) {
                sh[nb][tid] = Hw[t1 * HH + tid];
                sF[nb][tid] = make_float2(Fw[((size_t)t1 * HH + row0) * HH + tid],
                                          Fw[((size_t)t1 * HH + row0 + 1) * HH + tid]);
            } else if (tid < HH + 2) {
                sfbh[nb][tid - HH] = Fb[t1 * HH + row0 + (tid - HH)];
            } else if (tid == HH + 2) {
                sfbh[nb][2] = Hb[t1];
            }
        }

        gbar();   // barrier 2: P/Wc complete
        cur ^= 1; pb ^= 1;
    }

    // ======================= prediction (32 steps) =======================
    for (int t = LBn; t < WLn; t++) {
        float2 tv = make_float2(0.f, 0.f);
        if (doT) {
            const float* Wcur = g_Wc[cur] + (size_t)k0 * WCP + j;
            #pragma unroll 32
            for (int kk = 0; kk < 64; kk++) {
                float2 f = sF[pb][k0 + kk];
                float w = Wcur[kk * WCP];
                tv.x += f.x * w; tv.y += f.y * w;
            }
            sTp[h][j] = tv;
        }
        __syncthreads();

        if (doT) {
            float wf = comp2(sTp[0][j], h) + comp2(sTp[1][j], h);
            if (j == 0) wf += sfbh[pb][h];
            g_Wc[cur ^ 1][myrow * WCP + j] = wf;
            sqp[h][j] = sh[pb][myrow] * wf;
        }
        __syncthreads();
        if (tid < WC)
            g_Vpart[t - LBn][c][tid] = sqp[0][tid] + sqp[1][tid];

        // prefetch next step params
        if (t + 1 < WLn) {
            const int t1 = t + 1, nb = pb ^ 1;
            if (tid < HH) {
                sh[nb][tid] = Hw[t1 * HH + tid];
                sF[nb][tid] = make_float2(Fw[((size_t)t1 * HH + row0) * HH + tid],
                                          Fw[((size_t)t1 * HH + row0 + 1) * HH + tid]);
            } else if (tid < HH + 2) {
                sfbh[nb][tid - HH] = Fb[t1 * HH + row0 + (tid - HH)];
            } else if (tid == HH + 2) {
                sfbh[nb][2] = Hb[t1];
            }
        }

        gbar();
        cur ^= 1; pb ^= 1;
    }

    // tail: CTA c < 32 reduces V row p = c (split across halves)
    if (c < PWn && doT) {
        float s = 0.f;
        const int cc0 = h * 32;
        #pragma unroll
        for (int i = 0; i < 32; i++) s += g_Vpart[c][cc0 + i][j];
        svp[h][j] = s;
    }
    __syncthreads();
    if (c < PWn && tid < WC) {
        float s = svp[0][tid] + svp[1][tid];
        if (tid == 0) s += Hb[LBn + c];
        g_V[c][tid] = s;
    }
}

// ---------------------------------------------------------------------------
// Kernel 3: out[b][p] = V[p][0] + sum_t V[p][1+t] x[b][t]
// warp = one batch row, lane = p -> coalesced stores.
// ---------------------------------------------------------------------------
__global__ void __launch_bounds__(256) out_gemm(
    const float* __restrict__ x, float* __restrict__ out)
{
    __shared__ float sV[PWn][WC];
    const int tid = threadIdx.x;
    for (int e = tid; e < PWn * WC; e += 256) {
        int p = e / WC, jj = e % WC;
        sV[p][jj] = g_V[p][jj];
    }
    __syncthreads();

    const int gid = blockIdx.x * 256 + tid;
    const int b = gid >> 5, p = gid & 31;
    const float* xr = x + (size_t)b * LBn;
    float acc = sV[p][0];
    #pragma unroll 8
    for (int tt = 0; tt < LBn; tt++)
        acc += sV[p][1 + tt] * __ldg(xr + tt);
    out[(size_t)b * PWn + p] = acc;
}

// ---------------------------------------------------------------------------
extern "C" void kernel_launch(void* const* d_in, const int* in_sizes, int n_in,
                              void* d_out, int out_size) {
    const float* x   = (const float*)d_in[0];
    const float* Fw  = (const float*)d_in[1];
    const float* Fb  = (const float*)d_in[2];
    const float* Hw  = (const float*)d_in[3];
    const float* Hb  = (const float*)d_in[4];
    const float* ist = (const float*)d_in[5];
    const float* icv = (const float*)d_in[6];
    const float* Q   = (const float*)d_in[7];
    const float* R   = (const float*)d_in[8];

    dim3 tgrid(WLn, 4);
    transpose_f<<<tgrid, 256>>>(Fw);
    kalman_persist<<<NCTA, TPB>>>(Fw, Fb, Hw, Hb, ist, icv, Q, R);
    out_gemm<<<(8192 * PWn) / 256, 256>>>(x, (float*)d_out);
}

// round 8
// speedup vs baseline: 2.5307x; 1.2762x over previous
#include <cuda_runtime.h>
#include <cuda_bf16.h>

#define HH   128
#define LBn  64
#define PWn  32
#define WLn  96
#define WC   65
#define WCP  68
#define NCTA 64
#define TPB  256

// ---------------- device scratch (no allocations allowed) ----------------
__device__ float g_FT[WLn * HH * HH];
__device__ float g_Pp[2][HH * HH];        // Ppred (pre-update covariance)
__device__ float g_Tg[2][HH * WCP];       // T (pre-update influence)
__device__ float g_vpart[2][NCTA][HH];    // partials of v = h^T Ppred
__device__ float g_qpart[2][NCTA][WCP];   // partials of q = h^T T
__device__ float g_urow[2][HH];           // u = Ppred h (full row vector)
__device__ float g_Vpart[PWn][NCTA][WCP];
__device__ float g_V[PWn][WCP];
__device__ unsigned int g_cnt;   // zero-init
__device__ unsigned int g_gen;   // zero-init

__device__ __forceinline__ float comp2(float2 v, int h) { return h ? v.y : v.x; }

// Grid barrier (proven protocol + nanosleep backoff). All NCTA CTAs
// co-resident (64 <= 148 SMs, 1 CTA/SM). __threadfence() (gpu scope) emits
// CCTL.IVALL -> L1 invalidated, so plain loads after the barrier observe
// other SMs' plain stores.
__device__ __forceinline__ void gbar() {
    __syncthreads();
    if (threadIdx.x == 0) {
        __threadfence();
        unsigned int g0 = atomicAdd(&g_gen, 0u);   // read BEFORE arriving
        unsigned int a  = atomicAdd(&g_cnt, 1u);
        if (a == NCTA - 1u) {
            atomicExch(&g_cnt, 0u);                // reset BEFORE release
            __threadfence();
            atomicExch(&g_gen, g0 + 1u);
        } else {
            while (atomicAdd(&g_gen, 0u) == g0) { __nanosleep(128); }
        }
        __threadfence();
    }
    __syncthreads();
}

// ---------------------------------------------------------------------------
// Kernel 1: transpose the 96 F matrices (128x128) into g_FT.
// ---------------------------------------------------------------------------
__global__ void __launch_bounds__(256) transpose_f(const float* __restrict__ Fw) {
    const int t  = blockIdx.x;
    const int ti = blockIdx.y;
    __shared__ float s[32][33];
    const float* src = Fw + (size_t)t * HH * HH;
    float* dst = g_FT + (size_t)t * HH * HH;
    const int x  = threadIdx.x & 31;
    const int y0 = threadIdx.x >> 5;
    for (int tj = 0; tj < 4; tj++) {
        #pragma unroll
        for (int yy = 0; yy < 32; yy += 8)
            s[y0 + yy][x] = src[(ti * 32 + y0 + yy) * HH + tj * 32 + x];
        __syncthreads();
        #pragma unroll
        for (int yy = 0; yy < 32; yy += 8)
            dst[(tj * 32 + y0 + yy) * HH + ti * 32 + x] = s[x][y0 + yy];
        __syncthreads();
    }
}

// ---------------------------------------------------------------------------
// Kernel 2: persistent Kalman recursion, ONE grid barrier per step.
// State across steps: pre-update pair (Ppred, T) + rank-1 ingredients:
//   v = h^T Ppred (column partials), q = h^T T, u = Ppred h (row vector).
// NOTE: Ppred is NOT symmetric here (Q, init_cov asymmetric), so u != v.
// Deferred correction applied at the next step:
//   F*P_new = F*Ppred - (F*u/S) v^T ;  F*Wc_new = F*T - (F*u/S) q~^T
//   S = R + sum_j h[j] u[j]
// CTA c owns rows {2c, 2c+1}; thread (j = tid&127, h = tid>>7).
// ---------------------------------------------------------------------------
__global__ void __launch_bounds__(TPB, 1) kalman_persist(
    const float* __restrict__ Fw, const float* __restrict__ Fb,
    const float* __restrict__ Hw, const float* __restrict__ Hb,
    const float* __restrict__ istate, const float* __restrict__ icov,
    const float* __restrict__ Q, const float* __restrict__ R)
{
    const int c = blockIdx.x, tid = threadIdx.x;
    const int j = tid & 127, h = tid >> 7;
    const int row0 = c * 2;
    const int k0 = h * 64;
    const int myrow = row0 + h;
    const bool doT = (j < WC);

    __shared__ float  sh[2][HH];      // H_w rows, double buffered
    __shared__ float2 sF[2][HH];      // owned F rows, double buffered
    __shared__ float  sfbh[2][4];     // [buf][0..1]=F_b rows, [2]=H_b
    __shared__ float2 sA1p[2][HH];    // raw A1 partials per k-half
    __shared__ float2 sA[HH];         // corrected A1
    __shared__ float2 sPp_s[2][HH];   // loopB partials
    __shared__ float2 sTp[2][WC];     // raw T partials
    __shared__ float  svp[2][HH];     // v staging / vpart staging
    __shared__ float  sqs[2][WC];     // q staging / qpart staging
    __shared__ float  sred[2][3][4];  // shuffle stages [half][S,FK0,FK1][warp]

    // ---- init ----
    const float qreg = Q[myrow * HH + j];      // Q is step-invariant: 1 load
    const float R0 = R[0];
    g_Pp[0][myrow * HH + j] = icov[myrow * HH + j];
    if (doT)
        g_Tg[0][myrow * WCP + j] = (j == 0) ? istate[myrow] : 0.f;
    // step-0 params into buffer 0
    if (tid < HH) {
        sh[0][tid] = Hw[tid];
        sF[0][tid] = make_float2(Fw[(size_t)row0 * HH + tid],
                                 Fw[(size_t)(row0 + 1) * HH + tid]);
    } else if (tid < HH + 2) {
        sfbh[0][tid - HH] = Fb[row0 + (tid - HH)];
    } else if (tid == HH + 2) {
        sfbh[0][2] = Hb[0];
    }
    int cur = 0, pb = 0;
    gbar();

    // ======================= filter (64 steps) =======================
    for (int t = 0; t < LBn; t++) {
        const bool corr = (t >= 1);
        const float hbprev = sfbh[pb ^ 1][2];

        // ---- raw loops: A1 = F*Ppred_prev, Traw = F*T_prev ----
        float2 a1 = make_float2(0.f, 0.f);
        float2 tv = make_float2(0.f, 0.f);
        {
            const float* Pc = g_Pp[cur] + (size_t)k0 * HH + j;
            const float* Tc = g_Tg[cur] + (size_t)k0 * WCP + j;
            #pragma unroll 32
            for (int kk = 0; kk < 64; kk++) {
                float2 f = sF[pb][k0 + kk];
                float p = Pc[kk * HH];
                a1.x += f.x * p; a1.y += f.y * p;
                if (doT) {
                    float w = Tc[kk * WCP];
                    tv.x += f.x * w; tv.y += f.y * w;
                }
            }
        }

        // ---- previous-step partial reductions (overlap with loop tail) ----
        float vs = 0.f, qs = 0.f, uval = 0.f;
        if (corr) {
            uval = g_urow[cur][j];                 // u = Ppred_prev h_prev
            const int cc0 = h * 32;
            #pragma unroll
            for (int i = 0; i < 32; i++) vs += g_vpart[cur][cc0 + i][j];
            if (doT) {
                #pragma unroll
                for (int i = 0; i < 32; i++) qs += g_qpart[cur][cc0 + i][j];
            }
        }

        sA1p[h][j] = a1;
        if (doT) sTp[h][j] = tv;
        svp[h][j] = vs;
        if (doT) sqs[h][j] = qs;
        __syncthreads();

        // ---- S, FK from u; v_j from vpart sums ----
        float v_j = 0.f, termS = 0.f, tf0 = 0.f, tf1 = 0.f;
        if (corr) {
            v_j = svp[0][j] + svp[1][j];
            termS = sh[pb ^ 1][j] * uval;          // h_{t-1}[j] * u[j]
            float2 f = sF[pb][j];                   // F_t[row][k=j]
            tf0 = f.x * uval; tf1 = f.y * uval;
        }
        #pragma unroll
        for (int o = 16; o > 0; o >>= 1) {
            termS += __shfl_xor_sync(0xffffffffu, termS, o);
            tf0   += __shfl_xor_sync(0xffffffffu, tf0, o);
            tf1   += __shfl_xor_sync(0xffffffffu, tf1, o);
        }
        if ((tid & 31) == 0) {
            const int w = (tid >> 5) & 3;
            sred[h][0][w] = termS; sred[h][1][w] = tf0; sred[h][2][w] = tf1;
        }
        __syncthreads();

        float FK0 = 0.f, FK1 = 0.f;
        if (corr) {
            float S = R0 + sred[h][0][0] + sred[h][0][1] + sred[h][0][2] + sred[h][0][3];
            float inv = 1.f / S;
            FK0 = (sred[h][1][0] + sred[h][1][1] + sred[h][1][2] + sred[h][1][3]) * inv;
            FK1 = (sred[h][2][0] + sred[h][2][1] + sred[h][2][2] + sred[h][2][3]) * inv;
        }
        float qt = 0.f;
        if (corr && doT)
            qt = sqs[0][j] + sqs[1][j]
               + (j == 0 ? hbprev : 0.f) - (j == t ? 1.f : 0.f);

        // ---- combine + corrections (right vector is v, NOT u) ----
        if (h == 0) {   // corrected A1 for both rows, all k columns
            float2 p0 = sA1p[0][j], p1 = sA1p[1][j];
            sA[j] = make_float2(p0.x + p1.x - FK0 * v_j,
                                p0.y + p1.y - FK1 * v_j);
        }
        float Tval = 0.f;
        if (doT) {
            Tval = comp2(sTp[0][j], h) + comp2(sTp[1][j], h)
                 - (h ? FK1 : FK0) * qt;
            if (j == 0) Tval += sfbh[pb][h];
        }
        __syncthreads();

        // ---- loopB: Ppred = A1 * F^T + Q ----
        float2 pr = make_float2(0.f, 0.f);
        {
            const float* FT = g_FT + (size_t)t * HH * HH + (size_t)k0 * HH + j;
            #pragma unroll 32
            for (int kk = 0; kk < 64; kk++) {
                float ft = FT[kk * HH];
                float2 a = sA[k0 + kk];
                pr.x += a.x * ft; pr.y += a.y * ft;
            }
        }
        sPp_s[h][j] = pr;
        __syncthreads();
        const float ppf = comp2(sPp_s[0][j], h) + comp2(sPp_s[1][j], h) + qreg;

        // ---- writes: Ppred rows, T rows, v/q partials, u rows ----
        const int nxt = cur ^ 1;
        g_Pp[nxt][myrow * HH + j] = ppf;
        if (doT) g_Tg[nxt][myrow * WCP + j] = Tval;
        const float hr = sh[pb][myrow];
        svp[h][j] = hr * ppf;
        if (doT) sqs[h][j] = hr * Tval;
        // u[myrow] = sum_j Ppred[myrow][j] * h_t[j]
        {
            float uv = ppf * sh[pb][j];
            #pragma unroll
            for (int o = 16; o > 0; o >>= 1)
                uv += __shfl_xor_sync(0xffffffffu, uv, o);
            if ((tid & 31) == 0) sred[h][0][(tid >> 5) & 3] = uv;
        }
        __syncthreads();
        if (tid < HH)
            g_vpart[nxt][c][tid] = svp[0][tid] + svp[1][tid];
        else if (tid - HH < WC)
            g_qpart[nxt][c][tid - HH] = sqs[0][tid - HH] + sqs[1][tid - HH];
        if (j == 0)
            g_urow[nxt][myrow] = sred[h][0][0] + sred[h][0][1]
                               + sred[h][0][2] + sred[h][0][3];

        // ---- prefetch step t+1 params (ordered by gbar's entry sync) ----
        {
            const int t1 = t + 1, nb = pb ^ 1;
            if (tid < HH) {
                sh[nb][tid] = Hw[t1 * HH + tid];
                sF[nb][tid] = make_float2(Fw[((size_t)t1 * HH + row0) * HH + tid],
                                          Fw[((size_t)t1 * HH + row0 + 1) * HH + tid]);
            } else if (tid < HH + 2) {
                sfbh[nb][tid - HH] = Fb[t1 * HH + row0 + (tid - HH)];
            } else if (tid == HH + 2) {
                sfbh[nb][2] = Hb[t1];
            }
        }

        gbar();
        cur ^= 1; pb ^= 1;
    }

    // ======================= prediction (32 steps) =======================
    for (int t = LBn; t < WLn; t++) {
        const bool corr = (t == LBn);   // correction only from filter step 63
        const float hbprev = sfbh[pb ^ 1][2];

        float2 tv = make_float2(0.f, 0.f);
        if (doT) {
            const float* Tc = g_Tg[cur] + (size_t)k0 * WCP + j;
            #pragma unroll 32
            for (int kk = 0; kk < 64; kk++) {
                float2 f = sF[pb][k0 + kk];
                float w = Tc[kk * WCP];
                tv.x += f.x * w; tv.y += f.y * w;
            }
        }
        float qs = 0.f, uval = 0.f;
        if (corr) {
            uval = g_urow[cur][j];
            if (doT) {
                const int cc0 = h * 32;
                #pragma unroll
                for (int i = 0; i < 32; i++) qs += g_qpart[cur][cc0 + i][j];
            }
        }
        if (doT) { sTp[h][j] = tv; sqs[h][j] = qs; }
        __syncthreads();

        float termS = 0.f, tf0 = 0.f, tf1 = 0.f;
        if (corr) {
            termS = sh[pb ^ 1][j] * uval;
            float2 f = sF[pb][j];
            tf0 = f.x * uval; tf1 = f.y * uval;
        }
        #pragma unroll
        for (int o = 16; o > 0; o >>= 1) {
            termS += __shfl_xor_sync(0xffffffffu, termS, o);
            tf0   += __shfl_xor_sync(0xffffffffu, tf0, o);
            tf1   += __shfl_xor_sync(0xffffffffu, tf1, o);
        }
        if ((tid & 31) == 0) {
            const int w = (tid >> 5) & 3;
            sred[h][0][w] = termS; sred[h][1][w] = tf0; sred[h][2][w] = tf1;
        }
        __syncthreads();

        float FK0 = 0.f, FK1 = 0.f;
        if (corr) {
            float S = R0 + sred[h][0][0] + sred[h][0][1] + sred[h][0][2] + sred[h][0][3];
            float inv = 1.f / S;
            FK0 = (sred[h][1][0] + sred[h][1][1] + sred[h][1][2] + sred[h][1][3]) * inv;
            FK1 = (sred[h][2][0] + sred[h][2][1] + sred[h][2][2] + sred[h][2][3]) * inv;
        }
        float qt = 0.f;
        if (corr && doT)
            qt = sqs[0][j] + sqs[1][j]
               + (j == 0 ? hbprev : 0.f) - (j == LBn ? 1.f : 0.f);

        float Tval = 0.f;
        if (doT) {
            Tval = comp2(sTp[0][j], h) + comp2(sTp[1][j], h)
                 - (h ? FK1 : FK0) * qt;
            if (j == 0) Tval += sfbh[pb][h];
        }
        __syncthreads();   // before reusing sqs for Vpart staging

        if (doT) {
            g_Tg[cur ^ 1][myrow * WCP + j] = Tval;
            sqs[h][j] = sh[pb][myrow] * Tval;
        }
        __syncthreads();
        if (tid < WC)
            g_Vpart[t - LBn][c][tid] = sqs[0][tid] + sqs[1][tid];

        if (t + 1 < WLn) {
            const int t1 = t + 1, nb = pb ^ 1;
            if (tid < HH) {
                sh[nb][tid] = Hw[t1 * HH + tid];
                sF[nb][tid] = make_float2(Fw[((size_t)t1 * HH + row0) * HH + tid],
                                          Fw[((size_t)t1 * HH + row0 + 1) * HH + tid]);
            } else if (tid < HH + 2) {
                sfbh[nb][tid - HH] = Fb[t1 * HH + row0 + (tid - HH)];
            } else if (tid == HH + 2) {
                sfbh[nb][2] = Hb[t1];
            }
        }

        gbar();
        cur ^= 1; pb ^= 1;
    }

    // tail: CTA c < 32 reduces V row p = c (split across halves)
    if (c < PWn && doT) {
        float s = 0.f;
        const int cc0 = h * 32;
        #pragma unroll
        for (int i = 0; i < 32; i++) s += g_Vpart[c][cc0 + i][j];
        svp[h][j] = s;
    }
    __syncthreads();
    if (c < PWn && tid < WC) {
        float s = svp[0][tid] + svp[1][tid];
        if (tid == 0) s += Hb[LBn + c];
        g_V[c][tid] = s;
    }
}

// ---------------------------------------------------------------------------
// Kernel 3: out[b][p] = V[p][0] + sum_t V[p][1+t] x[b][t]
// ---------------------------------------------------------------------------
__global__ void __launch_bounds__(256) out_gemm(
    const float* __restrict__ x, float* __restrict__ out)
{
    __shared__ float sV[PWn][WC];
    const int tid = threadIdx.x;
    for (int e = tid; e < PWn * WC; e += 256) {
        int p = e / WC, jj = e % WC;
        sV[p][jj] = g_V[p][jj];
    }
    __syncthreads();

    const int gid = blockIdx.x * 256 + tid;
    const int b = gid >> 5, p = gid & 31;
    const float* xr = x + (size_t)b * LBn;
    float acc = sV[p][0];
    #pragma unroll 8
    for (int tt = 0; tt < LBn; tt++)
        acc += sV[p][1 + tt] * __ldg(xr + tt);
    out[(size_t)b * PWn + p] = acc;
}

// ---------------------------------------------------------------------------
extern "C" void kernel_launch(void* const* d_in, const int* in_sizes, int n_in,
                              void* d_out, int out_size) {
    const float* x   = (const float*)d_in[0];
    const float* Fw  = (const float*)d_in[1];
    const float* Fb  = (const float*)d_in[2];
    const float* Hw  = (const float*)d_in[3];
    const float* Hb  = (const float*)d_in[4];
    const float* ist = (const float*)d_in[5];
    const float* icv = (const float*)d_in[6];
    const float* Q   = (const float*)d_in[7];
    const float* R   = (const float*)d_in[8];

    dim3 tgrid(WLn, 4);
    transpose_f<<<tgrid, 256>>>(Fw);
    kalman_persist<<<NCTA, TPB>>>(Fw, Fb, Hw, Hb, ist, icv, Q, R);
    out_gemm<<<(8192 * PWn) / 256, 256>>>(x, (float*)d_out);
}

// round 9
// speedup vs baseline: 3.0191x; 1.1930x over previous
#include <cuda_runtime.h>
#include <cuda_bf16.h>

#define HH   128
#define LBn  64
#define PWn  32
#define WLn  96
#define WC   65
#define WCP  68
#define NCTA 64
#define TPB  256

// ---------------- device scratch (no allocations allowed) ----------------
__device__ float g_FT[WLn * HH * HH];
__device__ float g_Pp[2][HH * HH];        // Ppred (pre-update covariance)
__device__ float g_Tg[2][HH * WCP];       // T (pre-update influence)
__device__ float g_vpart[2][NCTA][HH];    // partials of v = h^T Ppred
__device__ float g_qpart[2][NCTA][WCP];   // partials of q = h^T T
__device__ float g_urow[2][HH];           // u = Ppred h (full row vector)
__device__ float g_Wcf[HH * WCP];         // corrected Wc after filter step 63
__device__ float g_V[PWn][WCP];
__device__ unsigned int g_cnt;   // zero-init; self-resetting
__device__ unsigned int g_gen;   // zero-init; reset by pred_chains each run

__device__ __forceinline__ float comp2(float2 v, int h) { return h ? v.y : v.x; }

// Atomic acquire load (NOT an RMW: no LTS atomic-ALU serialization).
__device__ __forceinline__ unsigned int ldacq_u32(const unsigned int* p) {
    unsigned int v;
    asm volatile("ld.global.acquire.gpu.u32 %0, [%1];" : "=r"(v) : "l"(p) : "memory");
    return v;
}

// Grid barrier with ABSOLUTE generation n (0-based barrier index).
// All NCTA CTAs co-resident (64 <= 148 SMs, 1 CTA/SM).
// - arrive: fence + counting RMW on g_cnt (returning add, proven protocol)
// - release: last arriver resets cnt, fences, sets g_gen = n+1
// - wait: poll with acquire LOADS until g_gen >= n+1. Monotonic counter:
//   a stale read only polls longer, can never exit early (round-5 bug class
//   eliminated). __threadfence() after (CCTL.IVALL) makes other SMs' plain
//   stores visible to our plain loads.
__device__ __forceinline__ void gbar(unsigned int n) {
    __syncthreads();
    if (threadIdx.x == 0) {
        __threadfence();
        unsigned int a = atomicAdd(&g_cnt, 1u);
        if (a == NCTA - 1u) {
            atomicExch(&g_cnt, 0u);                // reset BEFORE release
            __threadfence();
            atomicExch(&g_gen, n + 1u);
        } else {
            while ((int)(ldacq_u32(&g_gen) - (n + 1u)) < 0) { __nanosleep(64); }
        }
        __threadfence();
    }
    __syncthreads();
}

// ---------------------------------------------------------------------------
// Kernel 1: transpose the 96 F matrices (128x128) into g_FT.
// ---------------------------------------------------------------------------
__global__ void __launch_bounds__(256) transpose_f(const float* __restrict__ Fw) {
    const int t  = blockIdx.x;
    const int ti = blockIdx.y;
    __shared__ float s[32][33];
    const float* src = Fw + (size_t)t * HH * HH;
    float* dst = g_FT + (size_t)t * HH * HH;
    const int x  = threadIdx.x & 31;
    const int y0 = threadIdx.x >> 5;
    for (int tj = 0; tj < 4; tj++) {
        #pragma unroll
        for (int yy = 0; yy < 32; yy += 8)
            s[y0 + yy][x] = src[(ti * 32 + y0 + yy) * HH + tj * 32 + x];
        __syncthreads();
        #pragma unroll
        for (int yy = 0; yy < 32; yy += 8)
            dst[(tj * 32 + y0 + yy) * HH + ti * 32 + x] = s[x][y0 + yy];
        __syncthreads();
    }
}

// ---------------------------------------------------------------------------
// Kernel 2: persistent Kalman FILTER (64 steps, one barrier each), then
// materialize the corrected influence matrix Wcf = T_63 - K_63 q~_63^T.
// Deferred rank-1 correction as in round 8 (v, q, u carried across barrier).
// CTA c owns rows {2c, 2c+1}; thread (j = tid&127, h = tid>>7).
// ---------------------------------------------------------------------------
__global__ void __launch_bounds__(TPB, 1) kalman_persist(
    const float* __restrict__ Fw, const float* __restrict__ Fb,
    const float* __restrict__ Hw, const float* __restrict__ Hb,
    const float* __restrict__ istate, const float* __restrict__ icov,
    const float* __restrict__ Q, const float* __restrict__ R)
{
    const int c = blockIdx.x, tid = threadIdx.x;
    const int j = tid & 127, h = tid >> 7;
    const int row0 = c * 2;
    const int k0 = h * 64;
    const int myrow = row0 + h;
    const bool doT = (j < WC);

    __shared__ float  sh[2][HH];      // H_w rows, double buffered
    __shared__ float2 sF[2][HH];      // owned F rows, double buffered
    __shared__ float  sfbh[2][4];     // [buf][0..1]=F_b rows, [2]=H_b
    __shared__ float2 sA1p[2][HH];    // raw A1 partials per k-half
    __shared__ float2 sA[HH];         // corrected A1
    __shared__ float2 sPp_s[2][HH];   // loopB partials
    __shared__ float2 sTp[2][WC];     // raw T partials
    __shared__ float  svp[2][HH];     // v staging / vpart staging
    __shared__ float  sqs[2][WC];     // q staging / qpart staging
    __shared__ float  sred[2][3][4];  // shuffle stages [half][S,FK0,FK1][warp]

    // ---- init ----
    const float qreg = Q[myrow * HH + j];      // Q is step-invariant: 1 load
    const float R0 = R[0];
    g_Pp[0][myrow * HH + j] = icov[myrow * HH + j];
    if (doT)
        g_Tg[0][myrow * WCP + j] = (j == 0) ? istate[myrow] : 0.f;
    // step-0 params into buffer 0
    if (tid < HH) {
        sh[0][tid] = Hw[tid];
        sF[0][tid] = make_float2(Fw[(size_t)row0 * HH + tid],
                                 Fw[(size_t)(row0 + 1) * HH + tid]);
    } else if (tid < HH + 2) {
        sfbh[0][tid - HH] = Fb[row0 + (tid - HH)];
    } else if (tid == HH + 2) {
        sfbh[0][2] = Hb[0];
    }
    int cur = 0, pb = 0;
    unsigned int nbar = 0;
    gbar(nbar++);

    // ======================= filter (64 steps) =======================
    for (int t = 0; t < LBn; t++) {
        const bool corr = (t >= 1);
        const float hbprev = sfbh[pb ^ 1][2];

        // ---- raw loops: A1 = F*Ppred_prev, Traw = F*T_prev ----
        float2 a1 = make_float2(0.f, 0.f);
        float2 tv = make_float2(0.f, 0.f);
        {
            const float* Pc = g_Pp[cur] + (size_t)k0 * HH + j;
            const float* Tc = g_Tg[cur] + (size_t)k0 * WCP + j;
            #pragma unroll 32
            for (int kk = 0; kk < 64; kk++) {
                float2 f = sF[pb][k0 + kk];
                float p = Pc[kk * HH];
                a1.x += f.x * p; a1.y += f.y * p;
                if (doT) {
                    float w = Tc[kk * WCP];
                    tv.x += f.x * w; tv.y += f.y * w;
                }
            }
        }

        // ---- previous-step partial reductions ----
        float vs = 0.f, qs = 0.f, uval = 0.f;
        if (corr) {
            uval = g_urow[cur][j];                 // u = Ppred_prev h_prev
            const int cc0 = h * 32;
            #pragma unroll
            for (int i = 0; i < 32; i++) vs += g_vpart[cur][cc0 + i][j];
            if (doT) {
                #pragma unroll
                for (int i = 0; i < 32; i++) qs += g_qpart[cur][cc0 + i][j];
            }
        }

        sA1p[h][j] = a1;
        if (doT) sTp[h][j] = tv;
        svp[h][j] = vs;
        if (doT) sqs[h][j] = qs;
        __syncthreads();

        // ---- S, FK from u; v_j from vpart sums ----
        float v_j = 0.f, termS = 0.f, tf0 = 0.f, tf1 = 0.f;
        if (corr) {
            v_j = svp[0][j] + svp[1][j];
            termS = sh[pb ^ 1][j] * uval;          // h_{t-1}[j] * u[j]
            float2 f = sF[pb][j];                   // F_t[row][k=j]
            tf0 = f.x * uval; tf1 = f.y * uval;
        }
        #pragma unroll
        for (int o = 16; o > 0; o >>= 1) {
            termS += __shfl_xor_sync(0xffffffffu, termS, o);
            tf0   += __shfl_xor_sync(0xffffffffu, tf0, o);
            tf1   += __shfl_xor_sync(0xffffffffu, tf1, o);
        }
        if ((tid & 31) == 0) {
            const int w = (tid >> 5) & 3;
            sred[h][0][w] = termS; sred[h][1][w] = tf0; sred[h][2][w] = tf1;
        }
        __syncthreads();

        float FK0 = 0.f, FK1 = 0.f;
        if (corr) {
            float S = R0 + sred[h][0][0] + sred[h][0][1] + sred[h][0][2] + sred[h][0][3];
            float inv = 1.f / S;
            FK0 = (sred[h][1][0] + sred[h][1][1] + sred[h][1][2] + sred[h][1][3]) * inv;
            FK1 = (sred[h][2][0] + sred[h][2][1] + sred[h][2][2] + sred[h][2][3]) * inv;
        }
        float qt = 0.f;
        if (corr && doT)
            qt = sqs[0][j] + sqs[1][j]
               + (j == 0 ? hbprev : 0.f) - (j == t ? 1.f : 0.f);

        // ---- combine + corrections (right vector is v, NOT u) ----
        if (h == 0) {
            float2 p0 = sA1p[0][j], p1 = sA1p[1][j];
            sA[j] = make_float2(p0.x + p1.x - FK0 * v_j,
                                p0.y + p1.y - FK1 * v_j);
        }
        float Tval = 0.f;
        if (doT) {
            Tval = comp2(sTp[0][j], h) + comp2(sTp[1][j], h)
                 - (h ? FK1 : FK0) * qt;
            if (j == 0) Tval += sfbh[pb][h];
        }
        __syncthreads();

        // ---- loopB: Ppred = A1 * F^T + Q ----
        float2 pr = make_float2(0.f, 0.f);
        {
            const float* FT = g_FT + (size_t)t * HH * HH + (size_t)k0 * HH + j;
            #pragma unroll 32
            for (int kk = 0; kk < 64; kk++) {
                float ft = FT[kk * HH];
                float2 a = sA[k0 + kk];
                pr.x += a.x * ft; pr.y += a.y * ft;
            }
        }
        sPp_s[h][j] = pr;
        __syncthreads();
        const float ppf = comp2(sPp_s[0][j], h) + comp2(sPp_s[1][j], h) + qreg;

        // ---- writes: Ppred rows, T rows, v/q partials, u rows ----
        const int nxt = cur ^ 1;
        g_Pp[nxt][myrow * HH + j] = ppf;
        if (doT) g_Tg[nxt][myrow * WCP + j] = Tval;
        const float hr = sh[pb][myrow];
        svp[h][j] = hr * ppf;
        if (doT) sqs[h][j] = hr * Tval;
        // u[myrow] = sum_j Ppred[myrow][j] * h_t[j]
        {
            float uv = ppf * sh[pb][j];
            #pragma unroll
            for (int o = 16; o > 0; o >>= 1)
                uv += __shfl_xor_sync(0xffffffffu, uv, o);
            if ((tid & 31) == 0) sred[h][0][(tid >> 5) & 3] = uv;
        }
        __syncthreads();
        if (tid < HH)
            g_vpart[nxt][c][tid] = svp[0][tid] + svp[1][tid];
        else if (tid - HH < WC)
            g_qpart[nxt][c][tid - HH] = sqs[0][tid - HH] + sqs[1][tid - HH];
        if (j == 0)
            g_urow[nxt][myrow] = sred[h][0][0] + sred[h][0][1]
                               + sred[h][0][2] + sred[h][0][3];

        // ---- prefetch step t+1 params (ordered by gbar's entry sync) ----
        {
            const int t1 = t + 1, nb = pb ^ 1;
            if (tid < HH) {
                sh[nb][tid] = Hw[t1 * HH + tid];
                sF[nb][tid] = make_float2(Fw[((size_t)t1 * HH + row0) * HH + tid],
                                          Fw[((size_t)t1 * HH + row0 + 1) * HH + tid]);
            } else if (tid < HH + 2) {
                sfbh[nb][tid - HH] = Fb[t1 * HH + row0 + (tid - HH)];
            } else if (tid == HH + 2) {
                sfbh[nb][2] = Hb[t1];
            }
        }

        gbar(nbar++);
        cur ^= 1; pb ^= 1;
    }

    // ---- materialize Wcf = T_63 - (u/S) q~^T (no barrier needed: last gbar
    //      already published all step-63 partials) ----
    {
        // h_63 lives in sh[pb^1]; Hb[63] in sfbh[pb^1][2]
        const float hb63 = sfbh[pb ^ 1][2];
        const float uj = g_urow[cur][j];
        float termS = sh[pb ^ 1][j] * uj;
        #pragma unroll
        for (int o = 16; o > 0; o >>= 1)
            termS += __shfl_xor_sync(0xffffffffu, termS, o);
        if ((tid & 31) == 0) sred[h][0][(tid >> 5) & 3] = termS;
        // q~ partial sums (split across halves)
        float qs = 0.f;
        if (doT) {
            const int cc0 = h * 32;
            #pragma unroll
            for (int i = 0; i < 32; i++) qs += g_qpart[cur][cc0 + i][j];
            sqs[h][j] = qs;
        }
        __syncthreads();
        const float S = R0 + sred[h][0][0] + sred[h][0][1]
                           + sred[h][0][2] + sred[h][0][3];
        if (doT) {
            const float Krow = g_urow[cur][myrow] / S;
            const float qt = sqs[0][j] + sqs[1][j]
                           + (j == 0 ? hb63 : 0.f) - (j == LBn ? 1.f : 0.f);
            g_Wcf[myrow * WCP + j] = g_Tg[cur][myrow * WCP + j] - Krow * qt;
        }
    }
}

// ---------------------------------------------------------------------------
// Kernel 3: prediction chains — CTA m computes V row m with NO grid barriers.
//   r = Hw[64+m]; bias = Hb[64+m]; for i = 64+m .. 64: bias += r.Fb_i; r = F_i^T r
//   V[m][j] = r^T Wcf[:,j]  (+bias on const column)
// Threads (j = tid&127, h = tid>>7) split the k-sum in halves.
// Also resets the grid-barrier state for the next graph replay.
// ---------------------------------------------------------------------------
__global__ void __launch_bounds__(256) pred_chains(
    const float* __restrict__ Fw, const float* __restrict__ Fb,
    const float* __restrict__ Hw, const float* __restrict__ Hb)
{
    const int m = blockIdx.x;
    const int tid = threadIdx.x;
    const int j = tid & 127, h = tid >> 7;
    const int k0 = h * 64;

    // reset barrier state for next run (persist kernel has fully completed)
    if (m == 0 && tid == 0) { g_gen = 0u; g_cnt = 0u; }

    __shared__ float r[2][HH];
    __shared__ float rp[2][HH];
    __shared__ float sfb[HH];
    __shared__ float sbias[2];

    if (tid < HH) r[0][tid] = Hw[(LBn + m) * HH + tid];
    float bias = Hb[LBn + m];
    __syncthreads();

    int rb = 0;
    for (int i = LBn + m; i >= LBn; --i) {
        if (tid < HH) sfb[tid] = Fb[i * HH + tid];
        __syncthreads();
        float rn = 0.f, bp = 0.f;
        const float* Fi = Fw + (size_t)i * HH * HH + (size_t)k0 * HH + j;
        #pragma unroll 16
        for (int kk = 0; kk < 64; kk++) {
            float rk = r[rb][k0 + kk];
            rn += Fi[kk * HH] * rk;
            bp += sfb[k0 + kk] * rk;
        }
        rp[h][j] = rn;
        if (j == 0) sbias[h] = bp;
        __syncthreads();
        if (tid < HH) r[rb ^ 1][tid] = rp[0][tid] + rp[1][tid];
        bias += sbias[0] + sbias[1];
        __syncthreads();
        rb ^= 1;
    }

    // V[m][j] = sum_k r[k] * Wcf[k][j]
    if (j < WC) {
        float vn = 0.f;
        const float* Wf = g_Wcf + (size_t)k0 * WCP + j;
        #pragma unroll 16
        for (int kk = 0; kk < 64; kk++)
            vn += Wf[kk * WCP] * r[rb][k0 + kk];
        rp[h][j] = vn;
    }
    __syncthreads();
    if (tid < WC) {
        float s = rp[0][tid] + rp[1][tid];
        if (tid == 0) s += bias;
        g_V[m][tid] = s;
    }
}

// ---------------------------------------------------------------------------
// Kernel 4: out[b][p] = V[p][0] + sum_t V[p][1+t] x[b][t]
// ---------------------------------------------------------------------------
__global__ void __launch_bounds__(256) out_gemm(
    const float* __restrict__ x, float* __restrict__ out)
{
    __shared__ float sV[PWn][WC];
    const int tid = threadIdx.x;
    for (int e = tid; e < PWn * WC; e += 256) {
        int p = e / WC, jj = e % WC;
        sV[p][jj] = g_V[p][jj];
    }
    __syncthreads();

    const int gid = blockIdx.x * 256 + tid;
    const int b = gid >> 5, p = gid & 31;
    const float* xr = x + (size_t)b * LBn;
    float acc = sV[p][0];
    #pragma unroll 8
    for (int tt = 0; tt < LBn; tt++)
        acc += sV[p][1 + tt] * __ldg(xr + tt);
    out[(size_t)b * PWn + p] = acc;
}

// ---------------------------------------------------------------------------
extern "C" void kernel_launch(void* const* d_in, const int* in_sizes, int n_in,
                              void* d_out, int out_size) {
    const float* x   = (const float*)d_in[0];
    const float* Fw  = (const float*)d_in[1];
    const float* Fb  = (const float*)d_in[2];
    const float* Hw  = (const float*)d_in[3];
    const float* Hb  = (const float*)d_in[4];
    const float* ist = (const float*)d_in[5];
    const float* icv = (const float*)d_in[6];
    const float* Q   = (const float*)d_in[7];
    const float* R   = (const float*)d_in[8];

    dim3 tgrid(WLn, 4);
    transpose_f<<<tgrid, 256>>>(Fw);
    kalman_persist<<<NCTA, TPB>>>(Fw, Fb, Hw, Hb, ist, icv, Q, R);
    pred_chains<<<PWn, 256>>>(Fw, Fb, Hw, Hb);
    out_gemm<<<(8192 * PWn) / 256, 256>>>(x, (float*)d_out);
}